// round 14
// baseline (speedup 1.0000x reference)
#include <cuda_runtime.h>
#include <cuda_fp16.h>
#include <cstdint>
#include <cstddef>

#define DIM      768
#define NH       12
#define HD       64
#define BB       8
#define SEQ      1024
#define M_TOT    (BB * SEQ)          // 8192
#define QKV_N    (3 * DIM)           // 2304
#define ATT_SCALE 0.125f
#define QB       256                 // q rows per attention CTA

// ---------------------------------------------------------------------------
// Scratch planes. Device globals: allocation-free.
// ---------------------------------------------------------------------------
__device__ __half g_x_hi[(size_t)M_TOT * DIM];
__device__ __half g_wqkv_hi[(size_t)QKV_N * DIM];
__device__ __half g_wproj_hi[(size_t)DIM * DIM];
__device__ __half g_qkv_hi[(size_t)M_TOT * QKV_N];
__device__ __half g_att_hi[(size_t)M_TOT * DIM];

// ---------------------------------------------------------------------------
// Helpers
// ---------------------------------------------------------------------------
__device__ __forceinline__ uint32_t sptr(const void* p) {
    return (uint32_t)__cvta_generic_to_shared(p);
}
__device__ __forceinline__ void cp16(void* dst, const void* src) {
    asm volatile("cp.async.cg.shared.global [%0], [%1], 16;"
                 :: "r"(sptr(dst)), "l"(src));
}
__device__ __forceinline__ void cp_commit() {
    asm volatile("cp.async.commit_group;");
}
template<int N>
__device__ __forceinline__ void cp_wait() {
    asm volatile("cp.async.wait_group %0;" :: "n"(N));
}
__device__ __forceinline__ void ldsm4(uint32_t r[4], uint32_t a) {
    asm volatile("ldmatrix.sync.aligned.m8n8.x4.shared.b16 {%0,%1,%2,%3}, [%4];"
                 : "=r"(r[0]), "=r"(r[1]), "=r"(r[2]), "=r"(r[3]) : "r"(a));
}
__device__ __forceinline__ void ldsm4t(uint32_t r[4], uint32_t a) {
    asm volatile("ldmatrix.sync.aligned.m8n8.x4.trans.shared.b16 {%0,%1,%2,%3}, [%4];"
                 : "=r"(r[0]), "=r"(r[1]), "=r"(r[2]), "=r"(r[3]) : "r"(a));
}
__device__ __forceinline__ void mma_f16(float c[4], const uint32_t a[4],
                                        uint32_t b0, uint32_t b1) {
    asm volatile(
        "mma.sync.aligned.m16n8k16.row.col.f32.f16.f16.f32 "
        "{%0,%1,%2,%3},{%4,%5,%6,%7},{%8,%9},{%0,%1,%2,%3};"
        : "+f"(c[0]), "+f"(c[1]), "+f"(c[2]), "+f"(c[3])
        : "r"(a[0]), "r"(a[1]), "r"(a[2]), "r"(a[3]), "r"(b0), "r"(b1));
}
__device__ __forceinline__ uint32_t pack_h(float a, float b) {
    __half2 t = __floats2half2_rn(a, b);
    return *reinterpret_cast<uint32_t*>(&t);
}

// ---------------------------------------------------------------------------
// Fused fp32 -> fp16 conversion for all three inputs (one launch).
// ---------------------------------------------------------------------------
#define N4_X   (M_TOT * DIM / 4)     // 1572864
#define N4_WQ  (QKV_N * DIM / 4)     //  442368
#define N4_WP  (DIM * DIM / 4)       //  147456
#define N4_ALL (N4_X + N4_WQ + N4_WP)

__global__ void to_half_all(const float4* __restrict__ x,
                            const float4* __restrict__ wq,
                            const float4* __restrict__ wp,
                            uint2* __restrict__ xh,
                            uint2* __restrict__ wqh,
                            uint2* __restrict__ wph) {
    int i = blockIdx.x * blockDim.x + threadIdx.x;
    const float4* src;
    uint2* dst;
    int j;
    if (i < N4_X)                { src = x;  dst = xh;  j = i; }
    else if (i < N4_X + N4_WQ)   { src = wq; dst = wqh; j = i - N4_X; }
    else if (i < N4_ALL)         { src = wp; dst = wph; j = i - N4_X - N4_WQ; }
    else return;
    float4 v = src[j];
    dst[j] = make_uint2(pack_h(v.x, v.y), pack_h(v.z, v.w));
}

// ---------------------------------------------------------------------------
// fp16 tensor-core GEMM, cp.async pipeline (ST stages), BK=64, CTA tile MTx128.
// C[M,N] = A[M,K] * B[N,K]^T. 8 warps (2m x 4n); warp tile (MT/2) x 32.
// ST=3: single __syncthreads per K-chunk. ST=2: classic two-sync.
// OUT=0: fp32 + bias. OUT=1: fp16 plane.
// ---------------------------------------------------------------------------
template<int MT, int ST> struct GemmSmemT {
    __half Ah[ST][MT][72], Bh[ST][128][72];
};
extern __shared__ __align__(1024) char smem_raw[];

template<int MT, int ST>
__device__ __forceinline__ void gemm_load_stage(
    GemmSmemT<MT, ST>& s, int st,
    const __half* __restrict__ Ah_g, const __half* __restrict__ Bh_g,
    int row0, int col0, int K, int k0, int tid)
{
#pragma unroll
    for (int l = 0; l < MT / 32; l++) {          // A: MT*8 slots
        int idx = tid + 256 * l;
        int r = idx >> 3, p = idx & 7;
        cp16(&s.Ah[st][r][p * 8], &Ah_g[(size_t)(row0 + r) * K + k0 + p * 8]);
    }
#pragma unroll
    for (int l = 0; l < 4; l++) {                // B: 1024 slots
        int idx = tid + 256 * l;
        int r = idx >> 3, p = idx & 7;
        cp16(&s.Bh[st][r][p * 8], &Bh_g[(size_t)(col0 + r) * K + k0 + p * 8]);
    }
}

template<int OUT, int MT, int ST>
__global__ void __launch_bounds__(256, (MT == 64) ? 3 : 2)
gemm_f16(const __half* __restrict__ Ah_g,
         const __half* __restrict__ Bh_g,
         const float* __restrict__ bias,
         __half* __restrict__ Ch,
         float* __restrict__ Cf,
         int M, int N, int K)
{
    GemmSmemT<MT, ST>& s = *reinterpret_cast<GemmSmemT<MT, ST>*>(smem_raw);
    constexpr int NMT = MT / 32;     // 16-row m-tiles per warp

    const int tid  = threadIdx.x;
    const int lane = tid & 31;
    const int w    = tid >> 5;
    const int wm   = w & 1;
    const int wn   = w >> 1;
    const int row0 = blockIdx.y * MT;
    const int col0 = blockIdx.x * 128;

    float acc[NMT][4][4];
#pragma unroll
    for (int a = 0; a < NMT; a++)
#pragma unroll
        for (int b = 0; b < 4; b++)
#pragma unroll
            for (int c = 0; c < 4; c++) acc[a][b][c] = 0.f;

    const int nk = K / 64;

    if (ST == 3) {
        gemm_load_stage(s, 0, Ah_g, Bh_g, row0, col0, K, 0, tid);
        cp_commit();
        gemm_load_stage(s, 1, Ah_g, Bh_g, row0, col0, K, 64, tid);
        cp_commit();
    } else {
        gemm_load_stage(s, 0, Ah_g, Bh_g, row0, col0, K, 0, tid);
        cp_commit();
    }

    int st = 0;
    for (int i = 0; i < nk; i++) {
        if (ST == 3) {
            if (i < nk - 1) cp_wait<1>(); else cp_wait<0>();
            __syncthreads();   // stage i visible; stage (i+2)%3 drained
            if (i + 2 < nk) {
                int ns = st + 2; if (ns >= 3) ns -= 3;
                gemm_load_stage(s, ns, Ah_g, Bh_g, row0, col0, K,
                                (i + 2) * 64, tid);
                cp_commit();
            }
        } else {
            if (i + 1 < nk) {
                gemm_load_stage(s, st ^ 1, Ah_g, Bh_g, row0, col0, K,
                                (i + 1) * 64, tid);
                cp_commit();
                cp_wait<1>();
            } else {
                cp_wait<0>();
            }
            __syncthreads();
        }

#pragma unroll
        for (int kk = 0; kk < 64; kk += 16) {
            uint32_t ah[NMT][4];
#pragma unroll
            for (int mt = 0; mt < NMT; mt++) {
                int r = (MT / 2) * wm + 16 * mt + (lane & 15);
                int c = kk + (lane >> 4) * 8;
                ldsm4(ah[mt], sptr(&s.Ah[st][r][c]));
            }
#pragma unroll
            for (int np = 0; np < 2; np++) {
                uint32_t bh[4];
                int r = 32 * wn + 16 * np + (lane & 7) + (lane >> 4) * 8;
                int c = kk + ((lane >> 3) & 1) * 8;
                ldsm4(bh, sptr(&s.Bh[st][r][c]));
#pragma unroll
                for (int mt = 0; mt < NMT; mt++) {
                    mma_f16(acc[mt][2 * np + 0], ah[mt], bh[0], bh[1]);
                    mma_f16(acc[mt][2 * np + 1], ah[mt], bh[2], bh[3]);
                }
            }
        }

        if (ST == 3) {
            if (++st == 3) st = 0;
        } else {
            __syncthreads();
            st ^= 1;
        }
    }

    // Epilogue
#pragma unroll
    for (int mt = 0; mt < NMT; mt++) {
#pragma unroll
        for (int nt = 0; nt < 4; nt++) {
            int gr = row0 + (MT / 2) * wm + 16 * mt + (lane >> 2);
            int gc = col0 + 32 * wn + 8 * nt + 2 * (lane & 3);
            const float* cc = acc[mt][nt];
            if (OUT == 1) {
                *reinterpret_cast<uint32_t*>(&Ch[(size_t)gr * N + gc]) =
                    pack_h(cc[0], cc[1]);
                *reinterpret_cast<uint32_t*>(&Ch[(size_t)(gr + 8) * N + gc]) =
                    pack_h(cc[2], cc[3]);
            } else {
                float b0 = bias[gc], b1 = bias[gc + 1];
                *reinterpret_cast<float2*>(&Cf[(size_t)gr * N + gc]) =
                    make_float2(cc[0] + b0, cc[1] + b1);
                *reinterpret_cast<float2*>(&Cf[(size_t)(gr + 8) * N + gc]) =
                    make_float2(cc[2] + b0, cc[3] + b1);
            }
        }
    }
}

// ---------------------------------------------------------------------------
// Fused quadratic-ReLU attention, single-plane fp16, 3-stage K/V pipeline,
// 256 threads (R11 best config). Pointers are pre-offset per batch; grid is
// (SEQ/QB, NH, 1).
// ---------------------------------------------------------------------------
struct AttnSmem {
    __half Kh[3][128][72], Vh[3][128][72];
};

__device__ __forceinline__ void load_tile72_async(
    __half (*dst)[72], const __half* __restrict__ src, int tid)
{
#pragma unroll
    for (int l = 0; l < 4; l++) {
        int idx = tid + 256 * l;
        int r = idx >> 3, p = idx & 7;
        cp16(&dst[r][p * 8], &src[(size_t)r * QKV_N + p * 8]);
    }
}

__global__ void __launch_bounds__(256, 1)
attn_mma(const __half* __restrict__ qkv_hi,   // pre-offset to batch
         const float* __restrict__ alpha,
         const float* __restrict__ beta,
         const float* __restrict__ gamma,
         __half* __restrict__ att_hi)         // pre-offset to batch
{
    AttnSmem& s = *reinterpret_cast<AttnSmem*>(smem_raw);
    const int tid  = threadIdx.x;
    const int lane = tid & 31;
    const int w    = tid >> 5;
    const int qt   = blockIdx.x;
    const int h    = blockIdx.y;
    const int q0   = qt * QB;
    const int NKT  = SEQ / 128;      // 8 key tiles

    const float av = alpha[h], bv = beta[h], gv = gamma[h];
    const size_t base = (size_t)h * HD;

    // Prologue: prefetch key tiles 0 and 1
    load_tile72_async(s.Kh[0], qkv_hi + base + DIM,     tid);
    load_tile72_async(s.Vh[0], qkv_hi + base + 2 * DIM, tid);
    cp_commit();
    {
        const size_t koff = base + (size_t)128 * QKV_N;
        load_tile72_async(s.Kh[1], qkv_hi + koff + DIM,     tid);
        load_tile72_async(s.Vh[1], qkv_hi + koff + 2 * DIM, tid);
        cp_commit();
    }

    // Q fragments from global (A-frag layout per 16x16 k-tile)
    uint32_t qh[2][4][4];
    {
        const int rb = q0 + 32 * w + (lane >> 2);
        const int cb = h * HD + 2 * (lane & 3);
#pragma unroll
        for (int rg = 0; rg < 2; rg++) {
#pragma unroll
            for (int kc = 0; kc < 4; kc++) {
                size_t o00 = (size_t)(rb + 16 * rg) * QKV_N + cb + 16 * kc;
                size_t o10 = o00 + 8 * QKV_N;
                qh[rg][kc][0] = *reinterpret_cast<const uint32_t*>(&qkv_hi[o00]);
                qh[rg][kc][1] = *reinterpret_cast<const uint32_t*>(&qkv_hi[o10]);
                qh[rg][kc][2] = *reinterpret_cast<const uint32_t*>(&qkv_hi[o00 + 8]);
                qh[rg][kc][3] = *reinterpret_cast<const uint32_t*>(&qkv_hi[o10 + 8]);
            }
        }
    }

    float O[2][8][4];
#pragma unroll
    for (int rg = 0; rg < 2; rg++)
#pragma unroll
        for (int j = 0; j < 8; j++)
#pragma unroll
            for (int q = 0; q < 4; q++) O[rg][j][q] = 0.f;
    float rs[2][2] = {{0.f, 0.f}, {0.f, 0.f}};

    int st = 0;
    for (int kt = 0; kt < NKT; kt++) {
        if (kt < NKT - 1) cp_wait<1>(); else cp_wait<0>();
        __syncthreads();
        if (kt + 2 < NKT) {
            int ns = st + 2; if (ns >= 3) ns -= 3;
            const size_t koff = base + (size_t)((kt + 2) * 128) * QKV_N;
            load_tile72_async(s.Kh[ns], qkv_hi + koff + DIM,     tid);
            load_tile72_async(s.Vh[ns], qkv_hi + koff + 2 * DIM, tid);
            cp_commit();
        }

#pragma unroll
        for (int rg = 0; rg < 2; rg++) {
            float S[16][4];
#pragma unroll
            for (int j = 0; j < 16; j++)
#pragma unroll
                for (int q = 0; q < 4; q++) S[j][q] = 0.f;

#pragma unroll
            for (int kc = 0; kc < 4; kc++) {
#pragma unroll
                for (int np = 0; np < 8; np++) {
                    uint32_t kh[4];
                    int r = 16 * np + (lane & 7) + (lane >> 4) * 8;
                    int c = 16 * kc + ((lane >> 3) & 1) * 8;
                    ldsm4(kh, sptr(&s.Kh[st][r][c]));
                    mma_f16(S[2 * np + 0], qh[rg][kc], kh[0], kh[1]);
                    mma_f16(S[2 * np + 1], qh[rg][kc], kh[2], kh[3]);
                }
            }

#pragma unroll
            for (int j = 0; j < 16; j++) {
#pragma unroll
                for (int q = 0; q < 4; q++) {
                    float z = S[j][q] * ATT_SCALE;
                    float p = fmaf(fmaf(av, z, bv), z, gv);
                    S[j][q] = fmaxf(p, 0.f);
                }
                rs[rg][0] += S[j][0] + S[j][1];
                rs[rg][1] += S[j][2] + S[j][3];
            }

#pragma unroll
            for (int c8 = 0; c8 < 8; c8++) {
                uint32_t ph[4];
                ph[0] = pack_h(S[2 * c8][0],     S[2 * c8][1]);
                ph[1] = pack_h(S[2 * c8][2],     S[2 * c8][3]);
                ph[2] = pack_h(S[2 * c8 + 1][0], S[2 * c8 + 1][1]);
                ph[3] = pack_h(S[2 * c8 + 1][2], S[2 * c8 + 1][3]);
#pragma unroll
                for (int ep = 0; ep < 4; ep++) {
                    uint32_t vh[4];
                    int r = 16 * c8 + (lane & 7) + ((lane >> 3) & 1) * 8;
                    int c = 16 * ep + (lane >> 4) * 8;
                    ldsm4t(vh, sptr(&s.Vh[st][r][c]));
                    mma_f16(O[rg][2 * ep + 0], ph, vh[0], vh[1]);
                    mma_f16(O[rg][2 * ep + 1], ph, vh[2], vh[3]);
                }
            }
        }
        if (++st == 3) st = 0;
    }

#pragma unroll
    for (int rg = 0; rg < 2; rg++) {
        float r0 = rs[rg][0], r1 = rs[rg][1];
        r0 += __shfl_xor_sync(0xffffffffu, r0, 1);
        r0 += __shfl_xor_sync(0xffffffffu, r0, 2);
        r1 += __shfl_xor_sync(0xffffffffu, r1, 1);
        r1 += __shfl_xor_sync(0xffffffffu, r1, 2);
        const float inv0 = 1.f / (r0 + 1e-6f);
        const float inv1 = 1.f / (r1 + 1e-6f);

        const int row = q0 + 32 * w + 16 * rg + (lane >> 2);
#pragma unroll
        for (int j = 0; j < 8; j++) {
            int ce = h * HD + 8 * j + 2 * (lane & 3);
            *reinterpret_cast<uint32_t*>(&att_hi[(size_t)row * DIM + ce]) =
                pack_h(O[rg][j][0] * inv0, O[rg][j][1] * inv0);
            *reinterpret_cast<uint32_t*>(&att_hi[(size_t)(row + 8) * DIM + ce]) =
                pack_h(O[rg][j][2] * inv1, O[rg][j][3] * inv1);
        }
    }
}

// ---------------------------------------------------------------------------
// Launch: per-batch QKV/attention pipelining via fork-join streams.
// ---------------------------------------------------------------------------
extern "C" void kernel_launch(void* const* d_in, const int* in_sizes, int n_in,
                              void* d_out, int out_size)
{
    const float* x      = (const float*)d_in[0];
    const float* w_qkv  = (const float*)d_in[1];
    const float* w_proj = (const float*)d_in[2];
    const float* b_proj = (const float*)d_in[3];
    const float* alpha  = (const float*)d_in[4];
    const float* beta   = (const float*)d_in[5];
    const float* gamma  = (const float*)d_in[6];
    float* out = (float*)d_out;

    __half *xh, *wqh, *wph, *qh, *ah;
    cudaGetSymbolAddress((void**)&xh,  g_x_hi);
    cudaGetSymbolAddress((void**)&wqh, g_wqkv_hi);
    cudaGetSymbolAddress((void**)&wph, g_wproj_hi);
    cudaGetSymbolAddress((void**)&qh,  g_qkv_hi);
    cudaGetSymbolAddress((void**)&ah,  g_att_hi);

    cudaFuncSetAttribute((const void*)gemm_f16<1, 128, 3>,
                         cudaFuncAttributeMaxDynamicSharedMemorySize,
                         (int)sizeof(GemmSmemT<128, 3>));
    cudaFuncSetAttribute((const void*)gemm_f16<0, 64, 2>,
                         cudaFuncAttributeMaxDynamicSharedMemorySize,
                         (int)sizeof(GemmSmemT<64, 2>));
    cudaFuncSetAttribute((const void*)attn_mma,
                         cudaFuncAttributeMaxDynamicSharedMemorySize,
                         (int)sizeof(AttnSmem));

    // Fork-join resources (host-side only; no device allocations).
    cudaStream_t s1;
    cudaStreamCreateWithFlags(&s1, cudaStreamNonBlocking);
    cudaEvent_t ev[BB], evJoin;
    for (int b = 0; b < BB; b++)
        cudaEventCreateWithFlags(&ev[b], cudaEventDisableTiming);
    cudaEventCreateWithFlags(&evJoin, cudaEventDisableTiming);

    // 0) fp32 -> fp16 planes (stream 0)
    to_half_all<<<N4_ALL / 256, 256>>>((const float4*)x, (const float4*)w_qkv,
                                       (const float4*)w_proj,
                                       (uint2*)xh, (uint2*)wqh, (uint2*)wph);

    // 1+2) Pipelined per-batch: QKV slab b on stream 0, attention b on s1.
    for (int b = 0; b < BB; b++) {
        dim3 gq(QKV_N / 128, SEQ / 128);
        gemm_f16<1, 128, 3><<<gq, 256, sizeof(GemmSmemT<128, 3>)>>>(
            xh + (size_t)b * SEQ * DIM, wqh, nullptr,
            qh + (size_t)b * SEQ * QKV_N, nullptr, SEQ, QKV_N, DIM);
        cudaEventRecord(ev[b], 0);
        cudaStreamWaitEvent(s1, ev[b], 0);
        dim3 ga(SEQ / QB, NH, 1);
        attn_mma<<<ga, 256, sizeof(AttnSmem), s1>>>(
            qh + (size_t)b * SEQ * QKV_N, alpha, beta, gamma,
            ah + (size_t)b * SEQ * DIM);
    }
    cudaEventRecord(evJoin, s1);
    cudaStreamWaitEvent(0, evJoin, 0);

    // 3) Output projection + bias -> fp32 out (stream 0)
    {
        dim3 grid(DIM / 128, M_TOT / 64);
        gemm_f16<0, 64, 2><<<grid, 256, sizeof(GemmSmemT<64, 2>)>>>(
            ah, wph, b_proj, nullptr, out, M_TOT, DIM, DIM);
    }
}

// round 15
// speedup vs baseline: 1.3045x; 1.3045x over previous
#include <cuda_runtime.h>
#include <cuda_fp16.h>
#include <cstdint>
#include <cstddef>

#define DIM      768
#define NH       12
#define HD       64
#define BB       8
#define SEQ      1024
#define M_TOT    (BB * SEQ)          // 8192
#define QKV_N    (3 * DIM)           // 2304
#define ATT_SCALE 0.125f
#define QB       256                 // q rows per attention CTA

// ---------------------------------------------------------------------------
// Scratch planes. Device globals: allocation-free.
// ---------------------------------------------------------------------------
__device__ __half g_x_hi[(size_t)M_TOT * DIM];
__device__ __half g_wqkv_hi[(size_t)QKV_N * DIM];
__device__ __half g_wproj_hi[(size_t)DIM * DIM];
__device__ __half g_qkv_hi[(size_t)M_TOT * QKV_N];
__device__ __half g_att_hi[(size_t)M_TOT * DIM];

// ---------------------------------------------------------------------------
// Helpers
// ---------------------------------------------------------------------------
__device__ __forceinline__ uint32_t sptr(const void* p) {
    return (uint32_t)__cvta_generic_to_shared(p);
}
__device__ __forceinline__ void cp16(void* dst, const void* src) {
    asm volatile("cp.async.cg.shared.global [%0], [%1], 16;"
                 :: "r"(sptr(dst)), "l"(src));
}
__device__ __forceinline__ void cp_commit() {
    asm volatile("cp.async.commit_group;");
}
template<int N>
__device__ __forceinline__ void cp_wait() {
    asm volatile("cp.async.wait_group %0;" :: "n"(N));
}
__device__ __forceinline__ void ldsm4(uint32_t r[4], uint32_t a) {
    asm volatile("ldmatrix.sync.aligned.m8n8.x4.shared.b16 {%0,%1,%2,%3}, [%4];"
                 : "=r"(r[0]), "=r"(r[1]), "=r"(r[2]), "=r"(r[3]) : "r"(a));
}
__device__ __forceinline__ void ldsm4t(uint32_t r[4], uint32_t a) {
    asm volatile("ldmatrix.sync.aligned.m8n8.x4.trans.shared.b16 {%0,%1,%2,%3}, [%4];"
                 : "=r"(r[0]), "=r"(r[1]), "=r"(r[2]), "=r"(r[3]) : "r"(a));
}
__device__ __forceinline__ void mma_f16(float c[4], const uint32_t a[4],
                                        uint32_t b0, uint32_t b1) {
    asm volatile(
        "mma.sync.aligned.m16n8k16.row.col.f32.f16.f16.f32 "
        "{%0,%1,%2,%3},{%4,%5,%6,%7},{%8,%9},{%0,%1,%2,%3};"
        : "+f"(c[0]), "+f"(c[1]), "+f"(c[2]), "+f"(c[3])
        : "r"(a[0]), "r"(a[1]), "r"(a[2]), "r"(a[3]), "r"(b0), "r"(b1));
}
__device__ __forceinline__ uint32_t pack_h(float a, float b) {
    __half2 t = __floats2half2_rn(a, b);
    return *reinterpret_cast<uint32_t*>(&t);
}

// ---------------------------------------------------------------------------
// Fused fp32 -> fp16 conversion for all three inputs (one launch).
// ---------------------------------------------------------------------------
#define N4_X   (M_TOT * DIM / 4)     // 1572864
#define N4_WQ  (QKV_N * DIM / 4)     //  442368
#define N4_WP  (DIM * DIM / 4)       //  147456
#define N4_ALL (N4_X + N4_WQ + N4_WP)

__global__ void to_half_all(const float4* __restrict__ x,
                            const float4* __restrict__ wq,
                            const float4* __restrict__ wp,
                            uint2* __restrict__ xh,
                            uint2* __restrict__ wqh,
                            uint2* __restrict__ wph) {
    int i = blockIdx.x * blockDim.x + threadIdx.x;
    const float4* src;
    uint2* dst;
    int j;
    if (i < N4_X)                { src = x;  dst = xh;  j = i; }
    else if (i < N4_X + N4_WQ)   { src = wq; dst = wqh; j = i - N4_X; }
    else if (i < N4_ALL)         { src = wp; dst = wph; j = i - N4_X - N4_WQ; }
    else return;
    float4 v = src[j];
    dst[j] = make_uint2(pack_h(v.x, v.y), pack_h(v.z, v.w));
}

// ---------------------------------------------------------------------------
// fp16 tensor-core GEMM, cp.async pipeline (ST stages), BK=64, CTA tile MTx128.
// C[M,N] = A[M,K] * B[N,K]^T. 8 warps (2m x 4n); warp tile (MT/2) x 32.
// ST=3: single __syncthreads per K-chunk. ST=2: classic two-sync.
// OUT=0: fp32 + bias. OUT=1: fp16 plane.
// ---------------------------------------------------------------------------
template<int MT, int ST> struct GemmSmemT {
    __half Ah[ST][MT][72], Bh[ST][128][72];
};
extern __shared__ __align__(1024) char smem_raw[];

template<int MT, int ST>
__device__ __forceinline__ void gemm_load_stage(
    GemmSmemT<MT, ST>& s, int st,
    const __half* __restrict__ Ah_g, const __half* __restrict__ Bh_g,
    int row0, int col0, int K, int k0, int tid)
{
#pragma unroll
    for (int l = 0; l < MT / 32; l++) {          // A: MT*8 slots
        int idx = tid + 256 * l;
        int r = idx >> 3, p = idx & 7;
        cp16(&s.Ah[st][r][p * 8], &Ah_g[(size_t)(row0 + r) * K + k0 + p * 8]);
    }
#pragma unroll
    for (int l = 0; l < 4; l++) {                // B: 1024 slots
        int idx = tid + 256 * l;
        int r = idx >> 3, p = idx & 7;
        cp16(&s.Bh[st][r][p * 8], &Bh_g[(size_t)(col0 + r) * K + k0 + p * 8]);
    }
}

template<int OUT, int MT, int ST>
__global__ void __launch_bounds__(256, (MT == 64) ? 3 : 2)
gemm_f16(const __half* __restrict__ Ah_g,
         const __half* __restrict__ Bh_g,
         const float* __restrict__ bias,
         __half* __restrict__ Ch,
         float* __restrict__ Cf,
         int M, int N, int K)
{
    GemmSmemT<MT, ST>& s = *reinterpret_cast<GemmSmemT<MT, ST>*>(smem_raw);
    constexpr int NMT = MT / 32;     // 16-row m-tiles per warp

    const int tid  = threadIdx.x;
    const int lane = tid & 31;
    const int w    = tid >> 5;
    const int wm   = w & 1;
    const int wn   = w >> 1;
    const int row0 = blockIdx.y * MT;
    const int col0 = blockIdx.x * 128;

    float acc[NMT][4][4];
#pragma unroll
    for (int a = 0; a < NMT; a++)
#pragma unroll
        for (int b = 0; b < 4; b++)
#pragma unroll
            for (int c = 0; c < 4; c++) acc[a][b][c] = 0.f;

    const int nk = K / 64;

    if (ST == 3) {
        gemm_load_stage(s, 0, Ah_g, Bh_g, row0, col0, K, 0, tid);
        cp_commit();
        gemm_load_stage(s, 1, Ah_g, Bh_g, row0, col0, K, 64, tid);
        cp_commit();
    } else {
        gemm_load_stage(s, 0, Ah_g, Bh_g, row0, col0, K, 0, tid);
        cp_commit();
    }

    int st = 0;
    for (int i = 0; i < nk; i++) {
        if (ST == 3) {
            if (i < nk - 1) cp_wait<1>(); else cp_wait<0>();
            __syncthreads();   // stage i visible; stage (i+2)%3 drained
            if (i + 2 < nk) {
                int ns = st + 2; if (ns >= 3) ns -= 3;
                gemm_load_stage(s, ns, Ah_g, Bh_g, row0, col0, K,
                                (i + 2) * 64, tid);
                cp_commit();
            }
        } else {
            if (i + 1 < nk) {
                gemm_load_stage(s, st ^ 1, Ah_g, Bh_g, row0, col0, K,
                                (i + 1) * 64, tid);
                cp_commit();
                cp_wait<1>();
            } else {
                cp_wait<0>();
            }
            __syncthreads();
        }

#pragma unroll
        for (int kk = 0; kk < 64; kk += 16) {
            uint32_t ah[NMT][4];
#pragma unroll
            for (int mt = 0; mt < NMT; mt++) {
                int r = (MT / 2) * wm + 16 * mt + (lane & 15);
                int c = kk + (lane >> 4) * 8;
                ldsm4(ah[mt], sptr(&s.Ah[st][r][c]));
            }
#pragma unroll
            for (int np = 0; np < 2; np++) {
                uint32_t bh[4];
                int r = 32 * wn + 16 * np + (lane & 7) + (lane >> 4) * 8;
                int c = kk + ((lane >> 3) & 1) * 8;
                ldsm4(bh, sptr(&s.Bh[st][r][c]));
#pragma unroll
                for (int mt = 0; mt < NMT; mt++) {
                    mma_f16(acc[mt][2 * np + 0], ah[mt], bh[0], bh[1]);
                    mma_f16(acc[mt][2 * np + 1], ah[mt], bh[2], bh[3]);
                }
            }
        }

        if (ST == 3) {
            if (++st == 3) st = 0;
        } else {
            __syncthreads();
            st ^= 1;
        }
    }

    // Epilogue
#pragma unroll
    for (int mt = 0; mt < NMT; mt++) {
#pragma unroll
        for (int nt = 0; nt < 4; nt++) {
            int gr = row0 + (MT / 2) * wm + 16 * mt + (lane >> 2);
            int gc = col0 + 32 * wn + 8 * nt + 2 * (lane & 3);
            const float* cc = acc[mt][nt];
            if (OUT == 1) {
                *reinterpret_cast<uint32_t*>(&Ch[(size_t)gr * N + gc]) =
                    pack_h(cc[0], cc[1]);
                *reinterpret_cast<uint32_t*>(&Ch[(size_t)(gr + 8) * N + gc]) =
                    pack_h(cc[2], cc[3]);
            } else {
                float b0 = bias[gc], b1 = bias[gc + 1];
                *reinterpret_cast<float2*>(&Cf[(size_t)gr * N + gc]) =
                    make_float2(cc[0] + b0, cc[1] + b1);
                *reinterpret_cast<float2*>(&Cf[(size_t)(gr + 8) * N + gc]) =
                    make_float2(cc[2] + b0, cc[3] + b1);
            }
        }
    }
}

// ---------------------------------------------------------------------------
// Fused quadratic-ReLU attention, single-plane fp16, 3-stage K/V pipeline
// with one __syncthreads per key tile. 256 threads (R11 best config).
// CTA = 256 q-rows x (head, batch). 8 warps; warp w owns rows 32w..32w+31.
// ---------------------------------------------------------------------------
struct AttnSmem {
    __half Kh[3][128][72], Vh[3][128][72];
};

__device__ __forceinline__ void load_tile72_async(
    __half (*dst)[72], const __half* __restrict__ src, int tid)
{
#pragma unroll
    for (int l = 0; l < 4; l++) {
        int idx = tid + 256 * l;
        int r = idx >> 3, p = idx & 7;
        cp16(&dst[r][p * 8], &src[(size_t)r * QKV_N + p * 8]);
    }
}

__global__ void __launch_bounds__(256, 1)
attn_mma(const __half* __restrict__ qkv_hi,
         const float* __restrict__ alpha,
         const float* __restrict__ beta,
         const float* __restrict__ gamma,
         __half* __restrict__ att_hi)
{
    AttnSmem& s = *reinterpret_cast<AttnSmem*>(smem_raw);
    const int tid  = threadIdx.x;
    const int lane = tid & 31;
    const int w    = tid >> 5;
    const int qt   = blockIdx.x;
    const int h    = blockIdx.y;
    const int b    = blockIdx.z;
    const int q0   = qt * QB;
    const int NKT  = SEQ / 128;      // 8 key tiles

    const float av = alpha[h], bv = beta[h], gv = gamma[h];
    const size_t base = (size_t)(b * SEQ) * QKV_N + h * HD;

    // Prologue: prefetch key tiles 0 and 1
    load_tile72_async(s.Kh[0], qkv_hi + base + DIM,     tid);
    load_tile72_async(s.Vh[0], qkv_hi + base + 2 * DIM, tid);
    cp_commit();
    {
        const size_t koff = base + (size_t)128 * QKV_N;
        load_tile72_async(s.Kh[1], qkv_hi + koff + DIM,     tid);
        load_tile72_async(s.Vh[1], qkv_hi + koff + 2 * DIM, tid);
        cp_commit();
    }

    // Q fragments from global (A-frag layout per 16x16 k-tile)
    uint32_t qh[2][4][4];
    {
        const int rb = b * SEQ + q0 + 32 * w + (lane >> 2);
        const int cb = h * HD + 2 * (lane & 3);
#pragma unroll
        for (int rg = 0; rg < 2; rg++) {
#pragma unroll
            for (int kc = 0; kc < 4; kc++) {
                size_t o00 = (size_t)(rb + 16 * rg) * QKV_N + cb + 16 * kc;
                size_t o10 = o00 + 8 * QKV_N;
                qh[rg][kc][0] = *reinterpret_cast<const uint32_t*>(&qkv_hi[o00]);
                qh[rg][kc][1] = *reinterpret_cast<const uint32_t*>(&qkv_hi[o10]);
                qh[rg][kc][2] = *reinterpret_cast<const uint32_t*>(&qkv_hi[o00 + 8]);
                qh[rg][kc][3] = *reinterpret_cast<const uint32_t*>(&qkv_hi[o10 + 8]);
            }
        }
    }

    float O[2][8][4];
#pragma unroll
    for (int rg = 0; rg < 2; rg++)
#pragma unroll
        for (int j = 0; j < 8; j++)
#pragma unroll
            for (int q = 0; q < 4; q++) O[rg][j][q] = 0.f;
    float rs[2][2] = {{0.f, 0.f}, {0.f, 0.f}};

    int st = 0;
    for (int kt = 0; kt < NKT; kt++) {
        if (kt < NKT - 1) cp_wait<1>(); else cp_wait<0>();
        __syncthreads();
        if (kt + 2 < NKT) {
            int ns = st + 2; if (ns >= 3) ns -= 3;
            const size_t koff = base + (size_t)((kt + 2) * 128) * QKV_N;
            load_tile72_async(s.Kh[ns], qkv_hi + koff + DIM,     tid);
            load_tile72_async(s.Vh[ns], qkv_hi + koff + 2 * DIM, tid);
            cp_commit();
        }

#pragma unroll
        for (int rg = 0; rg < 2; rg++) {
            float S[16][4];
#pragma unroll
            for (int j = 0; j < 16; j++)
#pragma unroll
                for (int q = 0; q < 4; q++) S[j][q] = 0.f;

#pragma unroll
            for (int kc = 0; kc < 4; kc++) {
#pragma unroll
                for (int np = 0; np < 8; np++) {
                    uint32_t kh[4];
                    int r = 16 * np + (lane & 7) + (lane >> 4) * 8;
                    int c = 16 * kc + ((lane >> 3) & 1) * 8;
                    ldsm4(kh, sptr(&s.Kh[st][r][c]));
                    mma_f16(S[2 * np + 0], qh[rg][kc], kh[0], kh[1]);
                    mma_f16(S[2 * np + 1], qh[rg][kc], kh[2], kh[3]);
                }
            }

#pragma unroll
            for (int j = 0; j < 16; j++) {
#pragma unroll
                for (int q = 0; q < 4; q++) {
                    float z = S[j][q] * ATT_SCALE;
                    float p = fmaf(fmaf(av, z, bv), z, gv);
                    S[j][q] = fmaxf(p, 0.f);
                }
                rs[rg][0] += S[j][0] + S[j][1];
                rs[rg][1] += S[j][2] + S[j][3];
            }

#pragma unroll
            for (int c8 = 0; c8 < 8; c8++) {
                uint32_t ph[4];
                ph[0] = pack_h(S[2 * c8][0],     S[2 * c8][1]);
                ph[1] = pack_h(S[2 * c8][2],     S[2 * c8][3]);
                ph[2] = pack_h(S[2 * c8 + 1][0], S[2 * c8 + 1][1]);
                ph[3] = pack_h(S[2 * c8 + 1][2], S[2 * c8 + 1][3]);
#pragma unroll
                for (int ep = 0; ep < 4; ep++) {
                    uint32_t vh[4];
                    int r = 16 * c8 + (lane & 7) + ((lane >> 3) & 1) * 8;
                    int c = 16 * ep + (lane >> 4) * 8;
                    ldsm4t(vh, sptr(&s.Vh[st][r][c]));
                    mma_f16(O[rg][2 * ep + 0], ph, vh[0], vh[1]);
                    mma_f16(O[rg][2 * ep + 1], ph, vh[2], vh[3]);
                }
            }
        }
        if (++st == 3) st = 0;
    }

#pragma unroll
    for (int rg = 0; rg < 2; rg++) {
        float r0 = rs[rg][0], r1 = rs[rg][1];
        r0 += __shfl_xor_sync(0xffffffffu, r0, 1);
        r0 += __shfl_xor_sync(0xffffffffu, r0, 2);
        r1 += __shfl_xor_sync(0xffffffffu, r1, 1);
        r1 += __shfl_xor_sync(0xffffffffu, r1, 2);
        const float inv0 = 1.f / (r0 + 1e-6f);
        const float inv1 = 1.f / (r1 + 1e-6f);

        const int row = b * SEQ + q0 + 32 * w + 16 * rg + (lane >> 2);
#pragma unroll
        for (int j = 0; j < 8; j++) {
            int ce = h * HD + 8 * j + 2 * (lane & 3);
            *reinterpret_cast<uint32_t*>(&att_hi[(size_t)row * DIM + ce]) =
                pack_h(O[rg][j][0] * inv0, O[rg][j][1] * inv0);
            *reinterpret_cast<uint32_t*>(&att_hi[(size_t)(row + 8) * DIM + ce]) =
                pack_h(O[rg][j][2] * inv1, O[rg][j][3] * inv1);
        }
    }
}

// ---------------------------------------------------------------------------
// Launch (R11 best configuration: single stream, monolithic grids)
// ---------------------------------------------------------------------------
extern "C" void kernel_launch(void* const* d_in, const int* in_sizes, int n_in,
                              void* d_out, int out_size)
{
    const float* x      = (const float*)d_in[0];
    const float* w_qkv  = (const float*)d_in[1];
    const float* w_proj = (const float*)d_in[2];
    const float* b_proj = (const float*)d_in[3];
    const float* alpha  = (const float*)d_in[4];
    const float* beta   = (const float*)d_in[5];
    const float* gamma  = (const float*)d_in[6];
    float* out = (float*)d_out;

    __half *xh, *wqh, *wph, *qh, *ah;
    cudaGetSymbolAddress((void**)&xh,  g_x_hi);
    cudaGetSymbolAddress((void**)&wqh, g_wqkv_hi);
    cudaGetSymbolAddress((void**)&wph, g_wproj_hi);
    cudaGetSymbolAddress((void**)&qh,  g_qkv_hi);
    cudaGetSymbolAddress((void**)&ah,  g_att_hi);

    cudaFuncSetAttribute((const void*)gemm_f16<1, 128, 3>,
                         cudaFuncAttributeMaxDynamicSharedMemorySize,
                         (int)sizeof(GemmSmemT<128, 3>));
    cudaFuncSetAttribute((const void*)gemm_f16<0, 64, 2>,
                         cudaFuncAttributeMaxDynamicSharedMemorySize,
                         (int)sizeof(GemmSmemT<64, 2>));
    cudaFuncSetAttribute((const void*)attn_mma,
                         cudaFuncAttributeMaxDynamicSharedMemorySize,
                         (int)sizeof(AttnSmem));

    // 0) fp32 -> fp16 planes, one launch for all three tensors
    to_half_all<<<N4_ALL / 256, 256>>>((const float4*)x, (const float4*)w_qkv,
                                       (const float4*)w_proj,
                                       (uint2*)xh, (uint2*)wqh, (uint2*)wph);

    // 1) QKV projection -> fp16 plane (128x128, 3-stage, 1 sync/chunk)
    {
        dim3 grid(QKV_N / 128, M_TOT / 128);
        gemm_f16<1, 128, 3><<<grid, 256, sizeof(GemmSmemT<128, 3>)>>>(
            xh, wqh, nullptr, qh, nullptr, M_TOT, QKV_N, DIM);
    }

    // 2) Fused quadratic attention -> fp16 plane (256 threads, 3-stage K/V)
    {
        dim3 grid(SEQ / QB, NH, BB);
        attn_mma<<<grid, 256, sizeof(AttnSmem)>>>(qh, alpha, beta, gamma, ah);
    }

    // 3) Output projection + bias -> fp32 out (64x128, 2-stage, occ 3)
    {
        dim3 grid(DIM / 128, M_TOT / 64);
        gemm_f16<0, 64, 2><<<grid, 256, sizeof(GemmSmemT<64, 2>)>>>(
            ah, wph, b_proj, nullptr, out, M_TOT, DIM, DIM);
    }
}